// round 1
// baseline (speedup 1.0000x reference)
#include <cuda_runtime.h>
#include <cuda_bf16.h>
#include <math.h>

#define B_   4
#define S_   2048
#define DIMV 768
#define H_   16
#define DH   48
#define NROWS (B_ * S_)   // 8192

// Scratch (device globals: no allocation allowed in kernel_launch)
__device__ float g_q[B_ * H_ * S_ * DH];   // [b][h][s][d]
__device__ float g_k[B_ * H_ * S_ * DH];
__device__ float g_v[B_ * H_ * S_ * DH];
__device__ float g_o[NROWS * DIMV];        // [b][s][h*48+d] == [row][768]

// ---------------------------------------------------------------------------
// 64x64x16 tiled fp32 GEMM:  C[row][col] = sum_k A[row][k] * W[col][k] + bias[col]
// SCATTER=true writes into [B,H,S,48] layout instead of [row][768].
// ---------------------------------------------------------------------------
template<bool SCATTER>
__device__ __forceinline__ void gemm_body(const float* __restrict__ A,
                                          const float* __restrict__ W,
                                          const float* __restrict__ bias,
                                          float* __restrict__ C)
{
    __shared__ float As[16][64];
    __shared__ float Bs[16][64];

    const int tid  = threadIdx.x;
    const int row0 = blockIdx.y * 64;
    const int col0 = blockIdx.x * 64;
    const int lr   = tid >> 2;          // 0..63 (tile row for loads)
    const int lk   = (tid & 3) << 2;    // 0,4,8,12 (k offset for loads)
    const int tx   = tid & 15;
    const int ty   = tid >> 4;

    float acc[4][4];
    #pragma unroll
    for (int i = 0; i < 4; i++)
        #pragma unroll
        for (int j = 0; j < 4; j++) acc[i][j] = 0.f;

    const float* Aptr = A + (size_t)(row0 + lr) * DIMV + lk;
    const float* Wptr = W + (size_t)(col0 + lr) * DIMV + lk;

    for (int kt = 0; kt < DIMV; kt += 16) {
        float4 av = *(const float4*)(Aptr + kt);
        float4 wv = *(const float4*)(Wptr + kt);
        __syncthreads();
        As[lk + 0][lr] = av.x; As[lk + 1][lr] = av.y;
        As[lk + 2][lr] = av.z; As[lk + 3][lr] = av.w;
        Bs[lk + 0][lr] = wv.x; Bs[lk + 1][lr] = wv.y;
        Bs[lk + 2][lr] = wv.z; Bs[lk + 3][lr] = wv.w;
        __syncthreads();

        #pragma unroll
        for (int k = 0; k < 16; k++) {
            float4 a4 = *(const float4*)&As[k][ty << 2];
            float4 b4 = *(const float4*)&Bs[k][tx << 2];
            float ar[4] = {a4.x, a4.y, a4.z, a4.w};
            float br[4] = {b4.x, b4.y, b4.z, b4.w};
            #pragma unroll
            for (int i = 0; i < 4; i++)
                #pragma unroll
                for (int j = 0; j < 4; j++)
                    acc[i][j] += ar[i] * br[j];
        }
    }

    const int colb = col0 + (tx << 2);
    float4 bb = *(const float4*)&bias[colb];
    #pragma unroll
    for (int i = 0; i < 4; i++) {
        int row = row0 + (ty << 2) + i;
        float4 v;
        v.x = acc[i][0] + bb.x;
        v.y = acc[i][1] + bb.y;
        v.z = acc[i][2] + bb.z;
        v.w = acc[i][3] + bb.w;
        if (SCATTER) {
            // [b][h][s][d] layout; a 4-aligned float4 never crosses a head (48 % 4 == 0)
            int b = row >> 11, s = row & 2047;
            int h = colb / DH, d = colb % DH;
            size_t idx = (((size_t)(b * H_ + h) * S_ + s) * DH) + d;
            *(float4*)&C[idx] = v;
        } else {
            *(float4*)&C[(size_t)row * DIMV + colb] = v;
        }
    }
}

__global__ void __launch_bounds__(256) qkv_kernel(
    const float* __restrict__ x,
    const float* __restrict__ Wq, const float* __restrict__ bq,
    const float* __restrict__ Wk, const float* __restrict__ bk,
    const float* __restrict__ Wv, const float* __restrict__ bv)
{
    const float* W; const float* bias; float* out;
    if (blockIdx.z == 0)      { W = Wq; bias = bq; out = g_q; }
    else if (blockIdx.z == 1) { W = Wk; bias = bk; out = g_k; }
    else                      { W = Wv; bias = bv; out = g_v; }
    gemm_body<true>(x, W, bias, out);
}

__global__ void __launch_bounds__(256) proj_kernel(
    const float* __restrict__ Wo, const float* __restrict__ bo,
    float* __restrict__ out)
{
    gemm_body<false>(g_o, Wo, bo, out);
}

// ---------------------------------------------------------------------------
// Flash attention: block = (q-tile of 64, bh). 256 threads.
// 4 lanes per query; each lane owns 16 keys per K-tile and a private o[48]
// partial accumulator. m/l identical across the 4 lanes (width-4 shuffles).
// ---------------------------------------------------------------------------
__global__ void __launch_bounds__(256) attn_kernel()
{
    __shared__ float Qs[64 * DH];
    __shared__ float Ks[64 * DH];
    __shared__ float Vs[64 * DH];

    const int bh  = blockIdx.y;        // 0..63
    const int q0  = blockIdx.x * 64;
    const int tid = threadIdx.x;
    const int q   = tid >> 2;          // 0..63
    const int dg  = tid & 3;           // lane within query group

    const float* qbase = g_q + ((size_t)bh * S_ + q0) * DH;
    const float* kbase = g_k + (size_t)bh * S_ * DH;
    const float* vbase = g_v + (size_t)bh * S_ * DH;

    for (int i = tid; i < 64 * DH; i += 256) Qs[i] = qbase[i];

    float o[DH];
    #pragma unroll
    for (int d = 0; d < DH; d++) o[d] = 0.f;
    float m = -1e30f, l = 0.f;
    const float scale = 0.14433756729740643f;  // 1/sqrt(48)

    for (int kt = 0; kt < S_; kt += 64) {
        __syncthreads();  // prior tile fully consumed (also covers Q load, iter 0)
        for (int i = tid; i < 64 * DH; i += 256) {
            Ks[i] = kbase[(size_t)kt * DH + i];
            Vs[i] = vbase[(size_t)kt * DH + i];
        }
        __syncthreads();

        // scores for this lane's 16 keys
        float s[16];
        const float4* qp = (const float4*)&Qs[q * DH];
        #pragma unroll
        for (int j = 0; j < 16; j++) {
            int k = dg * 16 + j;
            const float4* kp = (const float4*)&Ks[k * DH];
            float acc = 0.f;
            #pragma unroll
            for (int d4 = 0; d4 < 12; d4++) {
                float4 a = qp[d4], b = kp[d4];
                acc += a.x * b.x + a.y * b.y + a.z * b.z + a.w * b.w;
            }
            s[j] = acc * scale;
        }

        float tmax = s[0];
        #pragma unroll
        for (int j = 1; j < 16; j++) tmax = fmaxf(tmax, s[j]);
        tmax = fmaxf(tmax, __shfl_xor_sync(0xffffffffu, tmax, 1, 4));
        tmax = fmaxf(tmax, __shfl_xor_sync(0xffffffffu, tmax, 2, 4));

        float mnew = fmaxf(m, tmax);
        float corr = __expf(m - mnew);
        float lsum = 0.f;
        #pragma unroll
        for (int j = 0; j < 16; j++) {
            s[j] = __expf(s[j] - mnew);
            lsum += s[j];
        }
        lsum += __shfl_xor_sync(0xffffffffu, lsum, 1, 4);
        lsum += __shfl_xor_sync(0xffffffffu, lsum, 2, 4);
        l = l * corr + lsum;
        m = mnew;

        #pragma unroll
        for (int d = 0; d < DH; d++) o[d] *= corr;

        #pragma unroll
        for (int j = 0; j < 16; j++) {
            int k = dg * 16 + j;
            float p = s[j];
            const float4* vp = (const float4*)&Vs[k * DH];
            #pragma unroll
            for (int d4 = 0; d4 < 12; d4++) {
                float4 v4 = vp[d4];
                o[d4 * 4 + 0] += p * v4.x;
                o[d4 * 4 + 1] += p * v4.y;
                o[d4 * 4 + 2] += p * v4.z;
                o[d4 * 4 + 3] += p * v4.w;
            }
        }
    }

    // combine the 4 lanes' key-partial accumulators
    #pragma unroll
    for (int d = 0; d < DH; d++) {
        float v = o[d];
        v += __shfl_xor_sync(0xffffffffu, v, 1, 4);
        v += __shfl_xor_sync(0xffffffffu, v, 2, 4);
        o[d] = v;
    }

    const float inv_l = 1.f / l;
    const int b = bh >> 4, h = bh & 15;
    const int srow = q0 + q;
    float* outp = g_o + ((size_t)(b * S_ + srow) * DIMV) + h * DH;
    #pragma unroll
    for (int dd = 0; dd < 12; dd++) {
        int d = dg * 12 + dd;
        outp[d] = o[d] * inv_l;
    }
}

// ---------------------------------------------------------------------------
extern "C" void kernel_launch(void* const* d_in, const int* in_sizes, int n_in,
                              void* d_out, int out_size)
{
    const float* x  = (const float*)d_in[0];
    const float* Wq = (const float*)d_in[1];
    const float* bq = (const float*)d_in[2];
    const float* Wk = (const float*)d_in[3];
    const float* bk = (const float*)d_in[4];
    const float* Wv = (const float*)d_in[5];
    const float* bv = (const float*)d_in[6];
    const float* Wo = (const float*)d_in[7];
    const float* bo = (const float*)d_in[8];
    float* out = (float*)d_out;

    dim3 gqkv(DIMV / 64, NROWS / 64, 3);     // 12 x 128 x 3
    qkv_kernel<<<gqkv, 256>>>(x, Wq, bq, Wk, bk, Wv, bv);

    dim3 gattn(S_ / 64, B_ * H_);            // 32 x 64
    attn_kernel<<<gattn, 256>>>();

    dim3 gproj(DIMV / 64, NROWS / 64);       // 12 x 128
    proj_kernel<<<gproj, 256>>>(Wo, bo, out);
}

// round 2
// speedup vs baseline: 6.8453x; 6.8453x over previous
#include <cuda_runtime.h>
#include <cuda_bf16.h>
#include <math.h>

#define B_   4
#define S_   2048
#define DIMV 768
#define H_   16
#define DH   48
#define NROWS (B_ * S_)   // 8192

// Scratch (device globals: no allocation allowed in kernel_launch)
__device__ float g_q[B_ * H_ * S_ * DH];   // [b][h][s][d]
__device__ float g_k[B_ * H_ * S_ * DH];
__device__ float g_v[B_ * H_ * S_ * DH];
__device__ float g_o[NROWS * DIMV];        // [b][s][h*48+d] == [row][768]

// ---------------------------------------------------------------------------
// tf32 helpers
// ---------------------------------------------------------------------------
__device__ __forceinline__ unsigned f2tf(float f) {
    unsigned u;
    asm("cvt.rna.tf32.f32 %0, %1;" : "=r"(u) : "f"(f));
    return u;
}

__device__ __forceinline__ void mma_tf32(float c[4], const unsigned a[4], const unsigned b[2]) {
    asm volatile(
        "mma.sync.aligned.m16n8k8.row.col.f32.tf32.tf32.f32 "
        "{%0,%1,%2,%3}, {%4,%5,%6,%7}, {%8,%9}, {%0,%1,%2,%3};\n"
        : "+f"(c[0]), "+f"(c[1]), "+f"(c[2]), "+f"(c[3])
        : "r"(a[0]), "r"(a[1]), "r"(a[2]), "r"(a[3]),
          "r"(b[0]), "r"(b[1]));
}

// ---------------------------------------------------------------------------
// 64x64x16 tiled fp32 GEMM:  C[row][col] = sum_k A[row][k] * W[col][k] + bias[col]
// SCATTER=true writes into [B,H,S,48] layout instead of [row][768].
// ---------------------------------------------------------------------------
template<bool SCATTER>
__device__ __forceinline__ void gemm_body(const float* __restrict__ A,
                                          const float* __restrict__ W,
                                          const float* __restrict__ bias,
                                          float* __restrict__ C)
{
    __shared__ float As[16][64];
    __shared__ float Bs[16][64];

    const int tid  = threadIdx.x;
    const int row0 = blockIdx.y * 64;
    const int col0 = blockIdx.x * 64;
    const int lr   = tid >> 2;
    const int lk   = (tid & 3) << 2;
    const int tx   = tid & 15;
    const int ty   = tid >> 4;

    float acc[4][4];
    #pragma unroll
    for (int i = 0; i < 4; i++)
        #pragma unroll
        for (int j = 0; j < 4; j++) acc[i][j] = 0.f;

    const float* Aptr = A + (size_t)(row0 + lr) * DIMV + lk;
    const float* Wptr = W + (size_t)(col0 + lr) * DIMV + lk;

    for (int kt = 0; kt < DIMV; kt += 16) {
        float4 av = *(const float4*)(Aptr + kt);
        float4 wv = *(const float4*)(Wptr + kt);
        __syncthreads();
        As[lk + 0][lr] = av.x; As[lk + 1][lr] = av.y;
        As[lk + 2][lr] = av.z; As[lk + 3][lr] = av.w;
        Bs[lk + 0][lr] = wv.x; Bs[lk + 1][lr] = wv.y;
        Bs[lk + 2][lr] = wv.z; Bs[lk + 3][lr] = wv.w;
        __syncthreads();

        #pragma unroll
        for (int k = 0; k < 16; k++) {
            float4 a4 = *(const float4*)&As[k][ty << 2];
            float4 b4 = *(const float4*)&Bs[k][tx << 2];
            float ar[4] = {a4.x, a4.y, a4.z, a4.w};
            float br[4] = {b4.x, b4.y, b4.z, b4.w};
            #pragma unroll
            for (int i = 0; i < 4; i++)
                #pragma unroll
                for (int j = 0; j < 4; j++)
                    acc[i][j] += ar[i] * br[j];
        }
    }

    const int colb = col0 + (tx << 2);
    float4 bbv = *(const float4*)&bias[colb];
    #pragma unroll
    for (int i = 0; i < 4; i++) {
        int row = row0 + (ty << 2) + i;
        float4 v;
        v.x = acc[i][0] + bbv.x;
        v.y = acc[i][1] + bbv.y;
        v.z = acc[i][2] + bbv.z;
        v.w = acc[i][3] + bbv.w;
        if (SCATTER) {
            int b = row >> 11, s = row & 2047;
            int h = colb / DH, d = colb % DH;
            size_t idx = (((size_t)(b * H_ + h) * S_ + s) * DH) + d;
            *(float4*)&C[idx] = v;
        } else {
            *(float4*)&C[(size_t)row * DIMV + colb] = v;
        }
    }
}

__global__ void __launch_bounds__(256) qkv_kernel(
    const float* __restrict__ x,
    const float* __restrict__ Wq, const float* __restrict__ bq,
    const float* __restrict__ Wk, const float* __restrict__ bk,
    const float* __restrict__ Wv, const float* __restrict__ bv)
{
    const float* W; const float* bias; float* out;
    if (blockIdx.z == 0)      { W = Wq; bias = bq; out = g_q; }
    else if (blockIdx.z == 1) { W = Wk; bias = bk; out = g_k; }
    else                      { W = Wv; bias = bv; out = g_v; }
    gemm_body<true>(x, W, bias, out);
}

__global__ void __launch_bounds__(256) proj_kernel(
    const float* __restrict__ Wo, const float* __restrict__ bo,
    float* __restrict__ out)
{
    gemm_body<false>(g_o, Wo, bo, out);
}

// ---------------------------------------------------------------------------
// Flash attention with tf32 mma.sync.m16n8k8.
// Block = 128 threads (4 warps); block handles (bh, 64-query tile);
// each warp owns 16 queries; key tiles of 64.
// Smem strides padded for conflict-free fragment loads:
//   K/Q stride 52, V stride 56, P stride 68.
// Q buffer aliases the per-warp P buffers (Q consumed into regs pre-loop).
// ---------------------------------------------------------------------------
#define KSTR 52
#define VSTR 56
#define PSTR 68

__global__ void __launch_bounds__(128) attn_kernel()
{
    __shared__ unsigned Ks[64 * KSTR];         // 13312 B
    __shared__ unsigned Vs[64 * VSTR];         // 14336 B
    __shared__ unsigned Buf[4 * 16 * PSTR];    // 17408 B: Q tile, then per-warp P

    const int bh   = blockIdx.y;       // 0..63
    const int q0   = blockIdx.x * 64;
    const int tid  = threadIdx.x;
    const int w    = tid >> 5;
    const int lane = tid & 31;
    const int g    = lane >> 2;        // groupID 0..7
    const int tig  = lane & 3;         // thread-in-group

    const float scale = 0.14433756729740643f;  // 1/sqrt(48)
    const float* qg = g_q + ((size_t)bh * S_ + q0) * DH;
    const float* kg = g_k + (size_t)bh * S_ * DH;
    const float* vg = g_v + (size_t)bh * S_ * DH;

    // ---- load Q tile (scaled, tf32) into Buf with stride KSTR ----
    for (int i4 = tid; i4 < 64 * DH / 4; i4 += 128) {
        int i = i4 * 4;
        int r = i / DH, c = i % DH;
        float4 v = *(const float4*)(qg + i);
        unsigned* dst = &Buf[r * KSTR + c];
        dst[0] = f2tf(v.x * scale); dst[1] = f2tf(v.y * scale);
        dst[2] = f2tf(v.z * scale); dst[3] = f2tf(v.w * scale);
    }
    __syncthreads();

    // ---- Q fragments (held in registers for the whole kernel) ----
    unsigned qa[6][4];
    {
        const int r0 = w * 16 + g;
        #pragma unroll
        for (int kf = 0; kf < 6; kf++) {
            const int c0 = kf * 8 + tig;
            qa[kf][0] = Buf[r0 * KSTR + c0];
            qa[kf][1] = Buf[(r0 + 8) * KSTR + c0];
            qa[kf][2] = Buf[r0 * KSTR + c0 + 4];
            qa[kf][3] = Buf[(r0 + 8) * KSTR + c0 + 4];
        }
    }

    float oc[6][4];
    #pragma unroll
    for (int nf = 0; nf < 6; nf++)
        #pragma unroll
        for (int j = 0; j < 4; j++) oc[nf][j] = 0.f;

    float m0 = -1e30f, m1 = -1e30f, l0 = 0.f, l1 = 0.f;
    unsigned* Pw = &Buf[w * 16 * PSTR];

    for (int kt = 0; kt < S_; kt += 64) {
        __syncthreads();   // prior tile consumed (covers Q-buffer reuse on iter 0)
        for (int i4 = tid; i4 < 64 * DH / 4; i4 += 128) {
            int i = i4 * 4;
            int r = i / DH, c = i % DH;
            float4 kv = *(const float4*)(kg + (size_t)kt * DH + i);
            float4 vv = *(const float4*)(vg + (size_t)kt * DH + i);
            unsigned* kd = &Ks[r * KSTR + c];
            kd[0] = f2tf(kv.x); kd[1] = f2tf(kv.y);
            kd[2] = f2tf(kv.z); kd[3] = f2tf(kv.w);
            unsigned* vd = &Vs[r * VSTR + c];
            vd[0] = f2tf(vv.x); vd[1] = f2tf(vv.y);
            vd[2] = f2tf(vv.z); vd[3] = f2tf(vv.w);
        }
        __syncthreads();

        // ---- scores: S[16 x 64] per warp ----
        float sc[8][4];
        #pragma unroll
        for (int n = 0; n < 8; n++) {
            sc[n][0] = sc[n][1] = sc[n][2] = sc[n][3] = 0.f;
            const int key = n * 8 + g;
            #pragma unroll
            for (int kf = 0; kf < 6; kf++) {
                unsigned bfr[2];
                bfr[0] = Ks[key * KSTR + kf * 8 + tig];
                bfr[1] = Ks[key * KSTR + kf * 8 + tig + 4];
                mma_tf32(sc[n], qa[kf], bfr);
            }
        }

        // ---- online softmax ----
        float rm0 = sc[0][0], rm1 = sc[0][2];
        #pragma unroll
        for (int n = 0; n < 8; n++) {
            rm0 = fmaxf(rm0, fmaxf(sc[n][0], sc[n][1]));
            rm1 = fmaxf(rm1, fmaxf(sc[n][2], sc[n][3]));
        }
        rm0 = fmaxf(rm0, __shfl_xor_sync(0xffffffffu, rm0, 1));
        rm0 = fmaxf(rm0, __shfl_xor_sync(0xffffffffu, rm0, 2));
        rm1 = fmaxf(rm1, __shfl_xor_sync(0xffffffffu, rm1, 1));
        rm1 = fmaxf(rm1, __shfl_xor_sync(0xffffffffu, rm1, 2));

        float nm0 = fmaxf(m0, rm0), nm1 = fmaxf(m1, rm1);
        float corr0 = __expf(m0 - nm0), corr1 = __expf(m1 - nm1);

        float ps0 = 0.f, ps1 = 0.f;
        __syncwarp();   // previous PV fragment loads done before P overwrite
        #pragma unroll
        for (int n = 0; n < 8; n++) {
            float p00 = __expf(sc[n][0] - nm0);
            float p01 = __expf(sc[n][1] - nm0);
            float p10 = __expf(sc[n][2] - nm1);
            float p11 = __expf(sc[n][3] - nm1);
            ps0 += p00 + p01;
            ps1 += p10 + p11;
            *(uint2*)&Pw[g * PSTR + n * 8 + 2 * tig]       = make_uint2(f2tf(p00), f2tf(p01));
            *(uint2*)&Pw[(g + 8) * PSTR + n * 8 + 2 * tig] = make_uint2(f2tf(p10), f2tf(p11));
        }
        ps0 += __shfl_xor_sync(0xffffffffu, ps0, 1);
        ps0 += __shfl_xor_sync(0xffffffffu, ps0, 2);
        ps1 += __shfl_xor_sync(0xffffffffu, ps1, 1);
        ps1 += __shfl_xor_sync(0xffffffffu, ps1, 2);

        l0 = l0 * corr0 + ps0;
        l1 = l1 * corr1 + ps1;
        m0 = nm0; m1 = nm1;

        #pragma unroll
        for (int nf = 0; nf < 6; nf++) {
            oc[nf][0] *= corr0; oc[nf][1] *= corr0;
            oc[nf][2] *= corr1; oc[nf][3] *= corr1;
        }
        __syncwarp();   // P stores visible to all lanes

        // ---- PV: O[16 x 48] += P[16 x 64] @ V[64 x 48] ----
        #pragma unroll
        for (int kf = 0; kf < 8; kf++) {
            unsigned pa[4];
            const int c0 = kf * 8 + tig;
            pa[0] = Pw[g * PSTR + c0];
            pa[1] = Pw[(g + 8) * PSTR + c0];
            pa[2] = Pw[g * PSTR + c0 + 4];
            pa[3] = Pw[(g + 8) * PSTR + c0 + 4];
            const int k0 = kf * 8 + tig;
            #pragma unroll
            for (int nf = 0; nf < 6; nf++) {
                unsigned bfr[2];
                bfr[0] = Vs[k0 * VSTR + nf * 8 + g];
                bfr[1] = Vs[(k0 + 4) * VSTR + nf * 8 + g];
                mma_tf32(oc[nf], pa, bfr);
            }
        }
    }

    // ---- epilogue ----
    const float inv0 = 1.f / l0, inv1 = 1.f / l1;
    const int bb = bh >> 4, h = bh & 15;
    const int row0 = q0 + w * 16 + g;
    float* ob  = g_o + (size_t)(bb * S_ + row0) * DIMV + h * DH;
    float* ob8 = ob + (size_t)8 * DIMV;
    #pragma unroll
    for (int nf = 0; nf < 6; nf++) {
        const int c = nf * 8 + 2 * tig;
        *(float2*)&ob[c]  = make_float2(oc[nf][0] * inv0, oc[nf][1] * inv0);
        *(float2*)&ob8[c] = make_float2(oc[nf][2] * inv1, oc[nf][3] * inv1);
    }
}

// ---------------------------------------------------------------------------
extern "C" void kernel_launch(void* const* d_in, const int* in_sizes, int n_in,
                              void* d_out, int out_size)
{
    const float* x  = (const float*)d_in[0];
    const float* Wq = (const float*)d_in[1];
    const float* bq = (const float*)d_in[2];
    const float* Wk = (const float*)d_in[3];
    const float* bk = (const float*)d_in[4];
    const float* Wv = (const float*)d_in[5];
    const float* bv = (const float*)d_in[6];
    const float* Wo = (const float*)d_in[7];
    const float* bo = (const float*)d_in[8];
    float* out = (float*)d_out;

    dim3 gqkv(DIMV / 64, NROWS / 64, 3);     // 12 x 128 x 3
    qkv_kernel<<<gqkv, 256>>>(x, Wq, bq, Wk, bk, Wv, bv);

    dim3 gattn(S_ / 64, B_ * H_);            // 32 x 64
    attn_kernel<<<gattn, 128>>>();

    dim3 gproj(DIMV / 64, NROWS / 64);       // 12 x 128
    proj_kernel<<<gproj, 256>>>(Wo, bo, out);
}

// round 3
// speedup vs baseline: 12.2030x; 1.7827x over previous
#include <cuda_runtime.h>
#include <cuda_bf16.h>
#include <math.h>

#define B_   4
#define S_   2048
#define DIMV 768
#define H_   16
#define DH   48
#define NROWS (B_ * S_)   // 8192

// Scratch (device globals: no allocation allowed in kernel_launch)
__device__ float g_q[B_ * H_ * S_ * DH];   // [b][h][s][d]
__device__ float g_k[B_ * H_ * S_ * DH];
__device__ float g_v[B_ * H_ * S_ * DH];
__device__ float g_o[NROWS * DIMV];        // [b][s][h*48+d] == [row][768]

// ---------------------------------------------------------------------------
// tf32 helpers
// ---------------------------------------------------------------------------
__device__ __forceinline__ unsigned f2tf(float f) {
    unsigned u;
    asm("cvt.rna.tf32.f32 %0, %1;" : "=r"(u) : "f"(f));
    return u;
}

__device__ __forceinline__ void mma_tf32(float c[4], const unsigned a[4], const unsigned b[2]) {
    asm volatile(
        "mma.sync.aligned.m16n8k8.row.col.f32.tf32.tf32.f32 "
        "{%0,%1,%2,%3}, {%4,%5,%6,%7}, {%8,%9}, {%0,%1,%2,%3};\n"
        : "+f"(c[0]), "+f"(c[1]), "+f"(c[2]), "+f"(c[3])
        : "r"(a[0]), "r"(a[1]), "r"(a[2]), "r"(a[3]),
          "r"(b[0]), "r"(b[1]));
}

// ---------------------------------------------------------------------------
// tf32 mma GEMM: C[row][col] = sum_k A[row][k] * W[col][k] + bias[col]
// Block: 256 threads (8 warps as 4(M) x 2(N)), tile 128x64, K-slab 32.
// Each warp: 32x32 = 2 m-frags x 4 n-frags of m16n8k8.
// SCATTER=true writes into [B,H,S,48] layout.
// ---------------------------------------------------------------------------
#define ASTR 36   // padded word stride: fragment banks (4g+tig)%32 all distinct

template<bool SCATTER>
__device__ __forceinline__ void gemm_mma_body(const float* __restrict__ A,
                                              const float* __restrict__ W,
                                              const float* __restrict__ bias,
                                              float* __restrict__ C)
{
    __shared__ unsigned As[128 * ASTR];   // 18432 B
    __shared__ unsigned Bs[64 * ASTR];    //  9216 B

    const int tid  = threadIdx.x;
    const int w    = tid >> 5;
    const int lane = tid & 31;
    const int g    = lane >> 2;
    const int tig  = lane & 3;
    const int wm   = w & 3;     // 0..3 : M position (32 rows)
    const int wn   = w >> 2;    // 0..1 : N position (32 cols)

    const int row0 = blockIdx.y * 128;
    const int col0 = blockIdx.x * 64;

    // gmem load mapping
    const int arow = tid >> 1;               // 0..127
    const int acol = (tid & 1) << 4;         // 0 or 16
    const float* Ap = A + (size_t)(row0 + arow) * DIMV + acol;
    const int brow0 = tid >> 3;              // 0..31  (and +32 for second half)
    const int bcol  = (tid & 7) << 2;        // 0,4,...,28
    const float* Wp = W + (size_t)(col0 + brow0) * DIMV + bcol;

    float acc[2][4][4];
    #pragma unroll
    for (int i = 0; i < 2; i++)
        #pragma unroll
        for (int j = 0; j < 4; j++)
            #pragma unroll
            for (int q = 0; q < 4; q++) acc[i][j][q] = 0.f;

    // prefetch first slab
    float4 ar[4], br[2];
    #pragma unroll
    for (int u = 0; u < 4; u++) ar[u] = *(const float4*)(Ap + u * 4);
    br[0] = *(const float4*)(Wp);
    br[1] = *(const float4*)(Wp + (size_t)32 * DIMV);

    for (int kt = 0; kt < DIMV; kt += 32) {
        __syncthreads();
        // store slab to smem (tf32)
        #pragma unroll
        for (int u = 0; u < 4; u++) {
            uint4 t;
            t.x = f2tf(ar[u].x); t.y = f2tf(ar[u].y);
            t.z = f2tf(ar[u].z); t.w = f2tf(ar[u].w);
            *(uint4*)&As[arow * ASTR + acol + u * 4] = t;
        }
        #pragma unroll
        for (int u = 0; u < 2; u++) {
            uint4 t;
            t.x = f2tf(br[u].x); t.y = f2tf(br[u].y);
            t.z = f2tf(br[u].z); t.w = f2tf(br[u].w);
            *(uint4*)&Bs[(brow0 + u * 32) * ASTR + bcol] = t;
        }
        __syncthreads();

        // prefetch next slab
        if (kt + 32 < DIMV) {
            #pragma unroll
            for (int u = 0; u < 4; u++) ar[u] = *(const float4*)(Ap + kt + 32 + u * 4);
            br[0] = *(const float4*)(Wp + kt + 32);
            br[1] = *(const float4*)(Wp + kt + 32 + (size_t)32 * DIMV);
        }

        // compute: 4 k-steps of 8
        #pragma unroll
        for (int ks = 0; ks < 4; ks++) {
            const int c0 = ks * 8 + tig;
            unsigned af[2][4];
            #pragma unroll
            for (int i = 0; i < 2; i++) {
                const int r0 = wm * 32 + i * 16 + g;
                af[i][0] = As[r0 * ASTR + c0];
                af[i][1] = As[(r0 + 8) * ASTR + c0];
                af[i][2] = As[r0 * ASTR + c0 + 4];
                af[i][3] = As[(r0 + 8) * ASTR + c0 + 4];
            }
            #pragma unroll
            for (int j = 0; j < 4; j++) {
                const int n0 = wn * 32 + j * 8 + g;
                unsigned bf[2];
                bf[0] = Bs[n0 * ASTR + c0];
                bf[1] = Bs[n0 * ASTR + c0 + 4];
                mma_tf32(acc[0][j], af[0], bf);
                mma_tf32(acc[1][j], af[1], bf);
            }
        }
    }

    // epilogue
    #pragma unroll
    for (int j = 0; j < 4; j++) {
        const int col = col0 + wn * 32 + j * 8 + 2 * tig;
        const float2 bb = *(const float2*)&bias[col];
        #pragma unroll
        for (int i = 0; i < 2; i++) {
            #pragma unroll
            for (int half = 0; half < 2; half++) {
                const int row = row0 + wm * 32 + i * 16 + g + half * 8;
                float2 v;
                v.x = acc[i][j][half * 2 + 0] + bb.x;
                v.y = acc[i][j][half * 2 + 1] + bb.y;
                if (SCATTER) {
                    int b = row >> 11, s = row & 2047;
                    int h = col / DH, d = col % DH;   // col even, never crosses head
                    size_t idx = (((size_t)(b * H_ + h) * S_ + s) * DH) + d;
                    *(float2*)&C[idx] = v;
                } else {
                    *(float2*)&C[(size_t)row * DIMV + col] = v;
                }
            }
        }
    }
}

__global__ void __launch_bounds__(256) qkv_kernel(
    const float* __restrict__ x,
    const float* __restrict__ Wq, const float* __restrict__ bq,
    const float* __restrict__ Wk, const float* __restrict__ bk,
    const float* __restrict__ Wv, const float* __restrict__ bv)
{
    const float* W; const float* bias; float* out;
    if (blockIdx.z == 0)      { W = Wq; bias = bq; out = g_q; }
    else if (blockIdx.z == 1) { W = Wk; bias = bk; out = g_k; }
    else                      { W = Wv; bias = bv; out = g_v; }
    gemm_mma_body<true>(x, W, bias, out);
}

__global__ void __launch_bounds__(256) proj_kernel(
    const float* __restrict__ Wo, const float* __restrict__ bo,
    float* __restrict__ out)
{
    gemm_mma_body<false>(g_o, Wo, bo, out);
}

// ---------------------------------------------------------------------------
// Flash attention with tf32 mma.sync.m16n8k8 (unchanged from R2).
// ---------------------------------------------------------------------------
#define KSTR 52
#define VSTR 56
#define PSTR 68

__global__ void __launch_bounds__(128) attn_kernel()
{
    __shared__ unsigned Ks[64 * KSTR];
    __shared__ unsigned Vs[64 * VSTR];
    __shared__ unsigned Buf[4 * 16 * PSTR];

    const int bh   = blockIdx.y;
    const int q0   = blockIdx.x * 64;
    const int tid  = threadIdx.x;
    const int w    = tid >> 5;
    const int lane = tid & 31;
    const int g    = lane >> 2;
    const int tig  = lane & 3;

    const float scale = 0.14433756729740643f;  // 1/sqrt(48)
    const float* qg = g_q + ((size_t)bh * S_ + q0) * DH;
    const float* kg = g_k + (size_t)bh * S_ * DH;
    const float* vg = g_v + (size_t)bh * S_ * DH;

    for (int i4 = tid; i4 < 64 * DH / 4; i4 += 128) {
        int i = i4 * 4;
        int r = i / DH, c = i % DH;
        float4 v = *(const float4*)(qg + i);
        unsigned* dst = &Buf[r * KSTR + c];
        dst[0] = f2tf(v.x * scale); dst[1] = f2tf(v.y * scale);
        dst[2] = f2tf(v.z * scale); dst[3] = f2tf(v.w * scale);
    }
    __syncthreads();

    unsigned qa[6][4];
    {
        const int r0 = w * 16 + g;
        #pragma unroll
        for (int kf = 0; kf < 6; kf++) {
            const int c0 = kf * 8 + tig;
            qa[kf][0] = Buf[r0 * KSTR + c0];
            qa[kf][1] = Buf[(r0 + 8) * KSTR + c0];
            qa[kf][2] = Buf[r0 * KSTR + c0 + 4];
            qa[kf][3] = Buf[(r0 + 8) * KSTR + c0 + 4];
        }
    }

    float oc[6][4];
    #pragma unroll
    for (int nf = 0; nf < 6; nf++)
        #pragma unroll
        for (int j = 0; j < 4; j++) oc[nf][j] = 0.f;

    float m0 = -1e30f, m1 = -1e30f, l0 = 0.f, l1 = 0.f;
    unsigned* Pw = &Buf[w * 16 * PSTR];

    for (int kt = 0; kt < S_; kt += 64) {
        __syncthreads();
        for (int i4 = tid; i4 < 64 * DH / 4; i4 += 128) {
            int i = i4 * 4;
            int r = i / DH, c = i % DH;
            float4 kv = *(const float4*)(kg + (size_t)kt * DH + i);
            float4 vv = *(const float4*)(vg + (size_t)kt * DH + i);
            unsigned* kd = &Ks[r * KSTR + c];
            kd[0] = f2tf(kv.x); kd[1] = f2tf(kv.y);
            kd[2] = f2tf(kv.z); kd[3] = f2tf(kv.w);
            unsigned* vd = &Vs[r * VSTR + c];
            vd[0] = f2tf(vv.x); vd[1] = f2tf(vv.y);
            vd[2] = f2tf(vv.z); vd[3] = f2tf(vv.w);
        }
        __syncthreads();

        float sc[8][4];
        #pragma unroll
        for (int n = 0; n < 8; n++) {
            sc[n][0] = sc[n][1] = sc[n][2] = sc[n][3] = 0.f;
            const int key = n * 8 + g;
            #pragma unroll
            for (int kf = 0; kf < 6; kf++) {
                unsigned bfr[2];
                bfr[0] = Ks[key * KSTR + kf * 8 + tig];
                bfr[1] = Ks[key * KSTR + kf * 8 + tig + 4];
                mma_tf32(sc[n], qa[kf], bfr);
            }
        }

        float rm0 = sc[0][0], rm1 = sc[0][2];
        #pragma unroll
        for (int n = 0; n < 8; n++) {
            rm0 = fmaxf(rm0, fmaxf(sc[n][0], sc[n][1]));
            rm1 = fmaxf(rm1, fmaxf(sc[n][2], sc[n][3]));
        }
        rm0 = fmaxf(rm0, __shfl_xor_sync(0xffffffffu, rm0, 1));
        rm0 = fmaxf(rm0, __shfl_xor_sync(0xffffffffu, rm0, 2));
        rm1 = fmaxf(rm1, __shfl_xor_sync(0xffffffffu, rm1, 1));
        rm1 = fmaxf(rm1, __shfl_xor_sync(0xffffffffu, rm1, 2));

        float nm0 = fmaxf(m0, rm0), nm1 = fmaxf(m1, rm1);
        float corr0 = __expf(m0 - nm0), corr1 = __expf(m1 - nm1);

        float ps0 = 0.f, ps1 = 0.f;
        __syncwarp();
        #pragma unroll
        for (int n = 0; n < 8; n++) {
            float p00 = __expf(sc[n][0] - nm0);
            float p01 = __expf(sc[n][1] - nm0);
            float p10 = __expf(sc[n][2] - nm1);
            float p11 = __expf(sc[n][3] - nm1);
            ps0 += p00 + p01;
            ps1 += p10 + p11;
            *(uint2*)&Pw[g * PSTR + n * 8 + 2 * tig]       = make_uint2(f2tf(p00), f2tf(p01));
            *(uint2*)&Pw[(g + 8) * PSTR + n * 8 + 2 * tig] = make_uint2(f2tf(p10), f2tf(p11));
        }
        ps0 += __shfl_xor_sync(0xffffffffu, ps0, 1);
        ps0 += __shfl_xor_sync(0xffffffffu, ps0, 2);
        ps1 += __shfl_xor_sync(0xffffffffu, ps1, 1);
        ps1 += __shfl_xor_sync(0xffffffffu, ps1, 2);

        l0 = l0 * corr0 + ps0;
        l1 = l1 * corr1 + ps1;
        m0 = nm0; m1 = nm1;

        #pragma unroll
        for (int nf = 0; nf < 6; nf++) {
            oc[nf][0] *= corr0; oc[nf][1] *= corr0;
            oc[nf][2] *= corr1; oc[nf][3] *= corr1;
        }
        __syncwarp();

        #pragma unroll
        for (int kf = 0; kf < 8; kf++) {
            unsigned pa[4];
            const int c0 = kf * 8 + tig;
            pa[0] = Pw[g * PSTR + c0];
            pa[1] = Pw[(g + 8) * PSTR + c0];
            pa[2] = Pw[g * PSTR + c0 + 4];
            pa[3] = Pw[(g + 8) * PSTR + c0 + 4];
            const int k0 = kf * 8 + tig;
            #pragma unroll
            for (int nf = 0; nf < 6; nf++) {
                unsigned bfr[2];
                bfr[0] = Vs[k0 * VSTR + nf * 8 + g];
                bfr[1] = Vs[(k0 + 4) * VSTR + nf * 8 + g];
                mma_tf32(oc[nf], pa, bfr);
            }
        }
    }

    const float inv0 = 1.f / l0, inv1 = 1.f / l1;
    const int bb = bh >> 4, h = bh & 15;
    const int row0 = q0 + w * 16 + g;
    float* ob  = g_o + (size_t)(bb * S_ + row0) * DIMV + h * DH;
    float* ob8 = ob + (size_t)8 * DIMV;
    #pragma unroll
    for (int nf = 0; nf < 6; nf++) {
        const int c = nf * 8 + 2 * tig;
        *(float2*)&ob[c]  = make_float2(oc[nf][0] * inv0, oc[nf][1] * inv0);
        *(float2*)&ob8[c] = make_float2(oc[nf][2] * inv1, oc[nf][3] * inv1);
    }
}

// ---------------------------------------------------------------------------
extern "C" void kernel_launch(void* const* d_in, const int* in_sizes, int n_in,
                              void* d_out, int out_size)
{
    const float* x  = (const float*)d_in[0];
    const float* Wq = (const float*)d_in[1];
    const float* bq = (const float*)d_in[2];
    const float* Wk = (const float*)d_in[3];
    const float* bk = (const float*)d_in[4];
    const float* Wv = (const float*)d_in[5];
    const float* bv = (const float*)d_in[6];
    const float* Wo = (const float*)d_in[7];
    const float* bo = (const float*)d_in[8];
    float* out = (float*)d_out;

    dim3 gqkv(DIMV / 64, NROWS / 128, 3);    // 12 x 64 x 3
    qkv_kernel<<<gqkv, 256>>>(x, Wq, bq, Wk, bk, Wv, bv);

    dim3 gattn(S_ / 64, B_ * H_);            // 32 x 64
    attn_kernel<<<gattn, 128>>>();

    dim3 gproj(DIMV / 64, NROWS / 128);      // 12 x 64
    proj_kernel<<<gproj, 256>>>(Wo, bo, out);
}